// round 12
// baseline (speedup 1.0000x reference)
#include <cuda_runtime.h>
#include <cuda_fp16.h>
#include <stdint.h>

#define NN 50000
#define NE 800000
#define DD 64

#define SCAN_T 1024
#define NCHUNK ((NN + SCAN_T - 1) / SCAN_T)   // 49

// scratch (no allocations allowed). Zero-initialized at module load.
// INVARIANT: g_cnt == 0 at entry of every kernel_launch call.
__device__ __half g_aggh[NN * DD];   // h_in = x + sum(neighbors), fp16
__device__ __half g_xh[NN * DD];     // fp16 copy of x
__device__ __half g_y0h[NN * DD];    // fp16 layer-0 output
__device__ int    g_cnt[NN];
__device__ int    g_rowptr[NN + 1];
__device__ unsigned g_col[NE];       // packed: src (low 16) | (dst&15)<<16
__device__ int    g_pos[NE];

// ---------------------------------------------------------------------------
// fused conv (x -> fp16) + degree histogram (records per-edge slot)
// ---------------------------------------------------------------------------
__global__ void __launch_bounds__(256)
convhist_kernel(const float* __restrict__ x, const int* __restrict__ dst) {
    int i = blockIdx.x * blockDim.x + threadIdx.x;
    if (i < NN * DD / 8) {
        float4 a = ((const float4*)x)[2 * i];
        float4 b = ((const float4*)x)[2 * i + 1];
        __half2 h[4];
        h[0] = __floats2half2_rn(a.x, a.y);
        h[1] = __floats2half2_rn(a.z, a.w);
        h[2] = __floats2half2_rn(b.x, b.y);
        h[3] = __floats2half2_rn(b.z, b.w);
        ((uint4*)g_xh)[i] = *(uint4*)h;
    }
    if (i < NE) {
        g_pos[i] = atomicAdd(&g_cnt[dst[i]], 1);
    }
}

// ---------------------------------------------------------------------------
// single-pass scan (block b redundantly reduces chunks [0,b) for its base)
// ---------------------------------------------------------------------------
__global__ void __launch_bounds__(SCAN_T)
scan_kernel() {
    __shared__ int s[SCAN_T];
    __shared__ int s_base;
    int b = blockIdx.x;
    int t = threadIdx.x;

    int pre = 0;
    for (int i = t; i < b * SCAN_T; i += SCAN_T) pre += g_cnt[i];
    s[t] = pre;
    __syncthreads();
    #pragma unroll
    for (int off = SCAN_T / 2; off > 0; off >>= 1) {
        if (t < off) s[t] += s[t + off];
        __syncthreads();
    }
    if (t == 0) s_base = s[0];
    __syncthreads();
    int base = s_base;
    __syncthreads();

    int i = b * SCAN_T + t;
    int v = (i < NN) ? g_cnt[i] : 0;
    s[t] = v;
    __syncthreads();
    #pragma unroll
    for (int off = 1; off < SCAN_T; off <<= 1) {
        int add = (t >= off) ? s[t - off] : 0;
        __syncthreads();
        s[t] += add;
        __syncthreads();
    }
    if (i < NN) g_rowptr[i + 1] = base + s[t];
    if (i == 0) g_rowptr[0] = 0;
}

// atomic-free fill; packs src + local-node-id; pos==0 edge resets g_cnt[d]
__global__ void fill_kernel(const int* __restrict__ src,
                            const int* __restrict__ dst) {
    int e = blockIdx.x * blockDim.x + threadIdx.x;
    if (e < NE) {
        int d = dst[e];
        int p = g_pos[e];
        g_col[g_rowptr[d] + p] =
            (unsigned)src[e] | ((unsigned)(d & 15) << 16);
        if (p == 0) g_cnt[d] = 0;
    }
}

// ---------------------------------------------------------------------------
// HMMA helpers (layouts identical to the validated MLP kernel)
// ---------------------------------------------------------------------------
__device__ __forceinline__ float fast_tanh(float x) {
    float y;
    asm("tanh.approx.f32 %0, %1;" : "=f"(y) : "f"(x));
    return y;
}

__device__ __forceinline__ void hmma(float* c, const uint32_t* a,
                                     uint32_t b0, uint32_t b1) {
    asm volatile(
        "mma.sync.aligned.m16n8k16.row.col.f32.f16.f16.f32 "
        "{%0,%1,%2,%3},{%4,%5,%6,%7},{%8,%9},{%0,%1,%2,%3};"
        : "+f"(c[0]), "+f"(c[1]), "+f"(c[2]), "+f"(c[3])
        : "r"(a[0]), "r"(a[1]), "r"(a[2]), "r"(a[3]), "r"(b0), "r"(b1));
}

__device__ __forceinline__ uint32_t pack_h2(float lo, float hi) {
    __half2 h = __floats2half2_rn(lo, hi);
    return *(uint32_t*)&h;
}

// ---------------------------------------------------------------------------
// MMA gather (SpMM): g_aggh[n] = X[n] + sum_{j in N(n)} X[j]
// block = 128 (4 warps); warp w owns 16 nodes (16-aligned range).
// Per 16-slot chunk: stage neighbor rows to smem, B via ldmatrix.x4.trans,
// one-hot A synthesized in registers, fp32 HMMA accumulation.
// ---------------------------------------------------------------------------
#define GS 72   // padded half-stride for staging rows (144B: 16B-aligned,
                // ldmatrix 8-row reads conflict-free)

__global__ void __launch_bounds__(128)
gather_kernel(int in_scratch) {
    __shared__ __half sbuf[4][16][GS];

    const __half* __restrict__ base = in_scratch ? g_y0h : g_xh;

    const int tid = threadIdx.x;
    const int w = tid >> 5;
    const int lane = tid & 31;
    const int g = lane >> 2;
    const int tg = lane & 3;

    const int a0g = blockIdx.x * 64 + w * 16;   // warp's first node (16-aligned)

    int lo = min(a0g, NN);
    int hi = min(a0g + 16, NN);
    int sbase = g_rowptr[lo];
    int send  = g_rowptr[hi];

    float c[8][4];
    #pragma unroll
    for (int nt = 0; nt < 8; nt++)
        #pragma unroll
        for (int j = 0; j < 4; j++) c[nt][j] = 0.f;

    uint32_t sb_addr = (uint32_t)__cvta_generic_to_shared(&sbuf[w][0][0]);
    const int srow = lane >> 3;           // 0..3
    const int scol = (lane & 7) * 8;      // half offset 0..56
    uint32_t lm_base = sb_addr + ((lane & 15) * GS + (lane >> 4) * 8) * 2;

    for (int sc = sbase; sc < send; sc += 16) {
        // ---- stage up to 16 neighbor rows (zero-fill tail) ----
        #pragma unroll
        for (int p = 0; p < 4; p++) {
            int row = p * 4 + srow;
            int s = sc + row;
            uint4 v = make_uint4(0, 0, 0, 0);
            if (s < send) {
                int j = (int)(g_col[s] & 0xFFFFu);
                v = *(const uint4*)(base + (size_t)j * DD + scol);
            }
            *(uint4*)(&sbuf[w][row][scol]) = v;
        }
        // ---- local node id of slots (lane k holds slot sc+k) ----
        int myn = -1;
        if (lane < 16 && sc + lane < send)
            myn = (int)(g_col[sc + lane] >> 16);
        __syncwarp();

        int k0 = tg * 2;
        int n00 = __shfl_sync(0xffffffffu, myn, k0);
        int n01 = __shfl_sync(0xffffffffu, myn, k0 + 1);
        int n10 = __shfl_sync(0xffffffffu, myn, k0 + 8);
        int n11 = __shfl_sync(0xffffffffu, myn, k0 + 9);

        uint32_t a[4];
        a[0] = (n00 == g     ? 0x3C00u : 0u) | (n01 == g     ? 0x3C000000u : 0u);
        a[1] = (n00 == g + 8 ? 0x3C00u : 0u) | (n01 == g + 8 ? 0x3C000000u : 0u);
        a[2] = (n10 == g     ? 0x3C00u : 0u) | (n11 == g     ? 0x3C000000u : 0u);
        a[3] = (n10 == g + 8 ? 0x3C00u : 0u) | (n11 == g + 8 ? 0x3C000000u : 0u);

        // ---- B fragments via ldmatrix.trans + MMA (8 n-tiles) ----
        #pragma unroll
        for (int ntp = 0; ntp < 4; ntp++) {
            uint32_t b0, b1, b2, b3;
            uint32_t addr = lm_base + (ntp * 16) * 2;
            asm volatile(
                "ldmatrix.sync.aligned.m8n8.x4.trans.shared.b16 "
                "{%0,%1,%2,%3}, [%4];"
                : "=r"(b0), "=r"(b1), "=r"(b2), "=r"(b3) : "r"(addr));
            hmma(c[2 * ntp],     a, b0, b1);
            hmma(c[2 * ntp + 1], a, b2, b3);
        }
        __syncwarp();
    }

    // ---- epilogue: add self row, convert, store fp16 ----
    int r0 = a0g + g;
    int r1 = r0 + 8;
    #pragma unroll
    for (int nt = 0; nt < 8; nt++) {
        int col = nt * 8 + tg * 2;
        if (r0 < NN) {
            uint32_t sv = *(const uint32_t*)(base + (size_t)r0 * DD + col);
            float2 f = __half22float2(*(__half2*)&sv);
            *(uint32_t*)(g_aggh + (size_t)r0 * DD + col) =
                pack_h2(c[nt][0] + f.x, c[nt][1] + f.y);
        }
        if (r1 < NN) {
            uint32_t sv = *(const uint32_t*)(base + (size_t)r1 * DD + col);
            float2 f = __half22float2(*(__half2*)&sv);
            *(uint32_t*)(g_aggh + (size_t)r1 * DD + col) =
                pack_h2(c[nt][2] + f.x, c[nt][3] + f.y);
        }
    }
}

// ---------------------------------------------------------------------------
// HMMA MLP (unchanged from round 11): out = tanh(T @ W1 + b1) @ W2 + b2
// ---------------------------------------------------------------------------
#define WS 72

__global__ void __launch_bounds__(128)
mlp_kernel(const float* __restrict__ w1, const float* __restrict__ b1,
           const float* __restrict__ w2, const float* __restrict__ b2,
           float* __restrict__ out, int out_half) {
    __shared__ __half sW1t[64 * WS];
    __shared__ __half sW2t[64 * WS];
    __shared__ __half sT[64 * WS];

    const int tid = threadIdx.x;
    const int n0 = blockIdx.x * 64;

    #pragma unroll 8
    for (int i = 0; i < 32; i++) {
        int id = i * 128 + tid;
        int k = id >> 6, n = id & 63;
        sW1t[n * WS + k] = __float2half(w1[id]);
        sW2t[n * WS + k] = __float2half(w2[id]);
    }

    #pragma unroll
    for (int i = 0; i < 4; i++) {
        int u4 = i * 128 + tid;
        int n = u4 >> 3;
        int c = (u4 & 7) * 8;
        uint4 v = make_uint4(0, 0, 0, 0);
        if (n0 + n < NN)
            v = *(const uint4*)(g_aggh + (size_t)(n0 + n) * DD + c);
        *(uint4*)(sT + n * WS + c) = v;
    }
    __syncthreads();

    const int w = tid >> 5;
    const int lane = tid & 31;
    const int g = lane >> 2;
    const int tg = lane & 3;
    const int row0 = w * 16 + g;
    const int row1 = row0 + 8;

    uint32_t a1f[4][4];
    #pragma unroll
    for (int kt = 0; kt < 4; kt++) {
        int k0 = kt * 16 + tg * 2;
        a1f[kt][0] = *(const uint32_t*)(sT + row0 * WS + k0);
        a1f[kt][1] = *(const uint32_t*)(sT + row1 * WS + k0);
        a1f[kt][2] = *(const uint32_t*)(sT + row0 * WS + k0 + 8);
        a1f[kt][3] = *(const uint32_t*)(sT + row1 * WS + k0 + 8);
    }

    float acc[8][4];

    #pragma unroll
    for (int nt = 0; nt < 8; nt++) {
        int col = nt * 8 + tg * 2;
        float2 bb = *(const float2*)(b1 + col);
        acc[nt][0] = bb.x; acc[nt][1] = bb.y;
        acc[nt][2] = bb.x; acc[nt][3] = bb.y;
        int cw = (nt * 8 + g) * WS;
        #pragma unroll
        for (int kt = 0; kt < 4; kt++) {
            int k0 = kt * 16 + tg * 2;
            uint32_t b0 = *(const uint32_t*)(sW1t + cw + k0);
            uint32_t b1r = *(const uint32_t*)(sW1t + cw + k0 + 8);
            hmma(acc[nt], a1f[kt], b0, b1r);
        }
    }

    uint32_t a2f[4][4];
    #pragma unroll
    for (int kt = 0; kt < 4; kt++) {
        int e = 2 * kt;
        a2f[kt][0] = pack_h2(fast_tanh(acc[e][0]),     fast_tanh(acc[e][1]));
        a2f[kt][1] = pack_h2(fast_tanh(acc[e][2]),     fast_tanh(acc[e][3]));
        a2f[kt][2] = pack_h2(fast_tanh(acc[e + 1][0]), fast_tanh(acc[e + 1][1]));
        a2f[kt][3] = pack_h2(fast_tanh(acc[e + 1][2]), fast_tanh(acc[e + 1][3]));
    }

    #pragma unroll
    for (int nt = 0; nt < 8; nt++) {
        int col = nt * 8 + tg * 2;
        float2 bb = *(const float2*)(b2 + col);
        acc[nt][0] = bb.x; acc[nt][1] = bb.y;
        acc[nt][2] = bb.x; acc[nt][3] = bb.y;
        int cw = (nt * 8 + g) * WS;
        #pragma unroll
        for (int kt = 0; kt < 4; kt++) {
            int k0 = kt * 16 + tg * 2;
            uint32_t b0 = *(const uint32_t*)(sW2t + cw + k0);
            uint32_t b1r = *(const uint32_t*)(sW2t + cw + k0 + 8);
            hmma(acc[nt], a2f[kt], b0, b1r);
        }
    }

    int gr0 = n0 + row0;
    int gr1 = n0 + row1;
    #pragma unroll
    for (int nt = 0; nt < 8; nt++) {
        int col = nt * 8 + tg * 2;
        if (out_half) {
            if (gr0 < NN)
                *(uint32_t*)(g_y0h + (size_t)gr0 * DD + col) =
                    pack_h2(acc[nt][0], acc[nt][1]);
            if (gr1 < NN)
                *(uint32_t*)(g_y0h + (size_t)gr1 * DD + col) =
                    pack_h2(acc[nt][2], acc[nt][3]);
        } else {
            if (gr0 < NN)
                *(float2*)(out + (size_t)gr0 * DD + col) =
                    make_float2(acc[nt][0], acc[nt][1]);
            if (gr1 < NN)
                *(float2*)(out + (size_t)gr1 * DD + col) =
                    make_float2(acc[nt][2], acc[nt][3]);
        }
    }
}

// ---------------------------------------------------------------------------
// launch — 7 kernels
// ---------------------------------------------------------------------------
extern "C" void kernel_launch(void* const* d_in, const int* in_sizes, int n_in,
                              void* d_out, int out_size) {
    const float* x    = (const float*)d_in[0];
    const int*   src  = (const int*)d_in[1];
    const int*   dst  = (const int*)d_in[2];
    const float* w1_0 = (const float*)d_in[3];
    const float* b1_0 = (const float*)d_in[4];
    const float* w2_0 = (const float*)d_in[5];
    const float* b2_0 = (const float*)d_in[6];
    const float* w1_1 = (const float*)d_in[7];
    const float* b1_1 = (const float*)d_in[8];
    const float* w2_1 = (const float*)d_in[9];
    const float* b2_1 = (const float*)d_in[10];
    float* out = (float*)d_out;

    const int edgeb = (NE + 255) / 256;
    const int tileb = (NN + 63) / 64;   // 782

    convhist_kernel<<<edgeb, 256>>>(x, dst);
    scan_kernel<<<NCHUNK, SCAN_T>>>();
    fill_kernel<<<edgeb, 256>>>(src, dst);

    gather_kernel<<<tileb, 128>>>(/*in_scratch=*/0);
    mlp_kernel<<<tileb, 128>>>(w1_0, b1_0, w2_0, b2_0, out, /*out_half=*/1);

    gather_kernel<<<tileb, 128>>>(/*in_scratch=*/1);
    mlp_kernel<<<tileb, 128>>>(w1_1, b1_1, w2_1, b2_1, out, /*out_half=*/0);
}

// round 14
// speedup vs baseline: 1.2962x; 1.2962x over previous
#include <cuda_runtime.h>
#include <cuda_fp16.h>
#include <stdint.h>

#define NN 50000
#define NE 800000
#define DD 64

#define SCAN_T 1024
#define NCHUNK ((NN + SCAN_T - 1) / SCAN_T)   // 49

// scratch (no allocations allowed). Zero-initialized at module load.
// INVARIANT: g_cnt == 0 at entry of every kernel_launch call.
__device__ __half g_aggh[NN * DD];   // h_in = x + sum(neighbors), fp16
__device__ __half g_xh[NN * DD];     // fp16 copy of x
__device__ __half g_y0h[NN * DD];    // fp16 layer-0 output
__device__ __half g_wt[2][2][64 * 64]; // [layer][w1|w2] transposed fp16: [n][k]
__device__ int    g_cnt[NN];
__device__ int    g_rowptr[NN + 1];
__device__ int    g_col[NE];
__device__ int    g_pos[NE];

// ---------------------------------------------------------------------------
// fused conv (x -> fp16) + weight conversion (fp32 -> fp16 transposed)
// + degree histogram (records per-edge slot)
// ---------------------------------------------------------------------------
__global__ void __launch_bounds__(256)
convhist_kernel(const float* __restrict__ x, const int* __restrict__ dst,
                const float* __restrict__ w1_0, const float* __restrict__ w2_0,
                const float* __restrict__ w1_1, const float* __restrict__ w2_1) {
    int i = blockIdx.x * blockDim.x + threadIdx.x;
    if (i < NN * DD / 8) {
        float4 a = ((const float4*)x)[2 * i];
        float4 b = ((const float4*)x)[2 * i + 1];
        __half2 h[4];
        h[0] = __floats2half2_rn(a.x, a.y);
        h[1] = __floats2half2_rn(a.z, a.w);
        h[2] = __floats2half2_rn(b.x, b.y);
        h[3] = __floats2half2_rn(b.z, b.w);
        ((uint4*)g_xh)[i] = *(uint4*)h;
    }
    if (i < 4096) {
        int k = i >> 6, n = i & 63;        // w[i] = W[k][n]
        int to = n * 64 + k;               // transposed [n][k]
        g_wt[0][0][to] = __float2half(w1_0[i]);
        g_wt[0][1][to] = __float2half(w2_0[i]);
        g_wt[1][0][to] = __float2half(w1_1[i]);
        g_wt[1][1][to] = __float2half(w2_1[i]);
    }
    if (i < NE) {
        g_pos[i] = atomicAdd(&g_cnt[dst[i]], 1);
    }
}

// ---------------------------------------------------------------------------
// single-pass scan (block b redundantly reduces chunks [0,b) for its base)
// ---------------------------------------------------------------------------
__global__ void __launch_bounds__(SCAN_T)
scan_kernel() {
    __shared__ int s[SCAN_T];
    __shared__ int s_base;
    int b = blockIdx.x;
    int t = threadIdx.x;

    int pre = 0;
    for (int i = t; i < b * SCAN_T; i += SCAN_T) pre += g_cnt[i];
    s[t] = pre;
    __syncthreads();
    #pragma unroll
    for (int off = SCAN_T / 2; off > 0; off >>= 1) {
        if (t < off) s[t] += s[t + off];
        __syncthreads();
    }
    if (t == 0) s_base = s[0];
    __syncthreads();
    int base = s_base;
    __syncthreads();

    int i = b * SCAN_T + t;
    int v = (i < NN) ? g_cnt[i] : 0;
    s[t] = v;
    __syncthreads();
    #pragma unroll
    for (int off = 1; off < SCAN_T; off <<= 1) {
        int add = (t >= off) ? s[t - off] : 0;
        __syncthreads();
        s[t] += add;
        __syncthreads();
    }
    if (i < NN) g_rowptr[i + 1] = base + s[t];
    if (i == 0) g_rowptr[0] = 0;
}

// atomic-free fill; pos==0 edge resets g_cnt[d] for the next call
__global__ void fill_kernel(const int* __restrict__ src,
                            const int* __restrict__ dst) {
    int e = blockIdx.x * blockDim.x + threadIdx.x;
    if (e < NE) {
        int d = dst[e];
        int p = g_pos[e];
        g_col[g_rowptr[d] + p] = src[e];
        if (p == 0) g_cnt[d] = 0;
    }
}

// ---------------------------------------------------------------------------
// fp16 gather (scalar, high occupancy — proven 16.8us):
// g_aggh[n] = X[n] + sum X[j]  (fp16 in, fp32 acc, fp16 out)
// ---------------------------------------------------------------------------
__device__ __forceinline__ void acc_add(float* a, uint4 v) {
    const __half2* h = (const __half2*)&v;
    #pragma unroll
    for (int i = 0; i < 4; i++) {
        float2 f = __half22float2(h[i]);
        a[2 * i]     += f.x;
        a[2 * i + 1] += f.y;
    }
}

__global__ void __launch_bounds__(256)
gather_kernel(int in_scratch) {
    const __half* __restrict__ base = in_scratch ? g_y0h : g_xh;
    int t = blockIdx.x * blockDim.x + threadIdx.x;
    int node = t >> 3;
    if (node >= NN) return;
    int colh = (t & 7) << 3;

    float acc[8] = {0.f};
    acc_add(acc, *(const uint4*)(base + (size_t)node * DD + colh));

    int p   = g_rowptr[node];
    int end = g_rowptr[node + 1];

    for (; p + 3 < end; p += 4) {
        int j0 = g_col[p];
        int j1 = g_col[p + 1];
        int j2 = g_col[p + 2];
        int j3 = g_col[p + 3];
        uint4 a = *(const uint4*)(base + (size_t)j0 * DD + colh);
        uint4 b = *(const uint4*)(base + (size_t)j1 * DD + colh);
        uint4 c = *(const uint4*)(base + (size_t)j2 * DD + colh);
        uint4 d = *(const uint4*)(base + (size_t)j3 * DD + colh);
        acc_add(acc, a);
        acc_add(acc, b);
        acc_add(acc, c);
        acc_add(acc, d);
    }
    for (; p < end; p++) {
        uint4 a = *(const uint4*)(base + (size_t)g_col[p] * DD + colh);
        acc_add(acc, a);
    }

    __half2 h[4];
    h[0] = __floats2half2_rn(acc[0], acc[1]);
    h[1] = __floats2half2_rn(acc[2], acc[3]);
    h[2] = __floats2half2_rn(acc[4], acc[5]);
    h[3] = __floats2half2_rn(acc[6], acc[7]);
    *(uint4*)(g_aggh + (size_t)node * DD + colh) = *(uint4*)h;
}

// ---------------------------------------------------------------------------
// HMMA MLP: out = tanh(T @ W1 + b1) @ W2 + b2, fp16 tensor cores, f32 acc.
// Weights pre-converted/transposed in gmem -> staging is pure uint4 copies.
// GEMM1 C-fragments ARE GEMM2 A-fragments -> tanh+repack in registers.
// ---------------------------------------------------------------------------
__device__ __forceinline__ float fast_tanh(float x) {
    float y;
    asm("tanh.approx.f32 %0, %1;" : "=f"(y) : "f"(x));
    return y;
}

__device__ __forceinline__ void hmma(float* c, const uint32_t* a,
                                     uint32_t b0, uint32_t b1) {
    asm volatile(
        "mma.sync.aligned.m16n8k16.row.col.f32.f16.f16.f32 "
        "{%0,%1,%2,%3},{%4,%5,%6,%7},{%8,%9},{%0,%1,%2,%3};"
        : "+f"(c[0]), "+f"(c[1]), "+f"(c[2]), "+f"(c[3])
        : "r"(a[0]), "r"(a[1]), "r"(a[2]), "r"(a[3]), "r"(b0), "r"(b1));
}

__device__ __forceinline__ uint32_t pack_h2(float lo, float hi) {
    __half2 h = __floats2half2_rn(lo, hi);
    return *(uint32_t*)&h;
}

#define WS 72   // padded half-stride (144B rows; conflict-free frag loads)

__global__ void __launch_bounds__(128)
mlp_kernel(const float* __restrict__ b1, const float* __restrict__ b2,
           float* __restrict__ out, int layer, int out_half) {
    __shared__ __half sW1t[64 * WS];   // sW1t[n][k] = W1[k][n]
    __shared__ __half sW2t[64 * WS];
    __shared__ __half sT[64 * WS];     // node tile, row-major fp16

    const __half* __restrict__ w1t = g_wt[layer][0];
    const __half* __restrict__ w2t = g_wt[layer][1];

    const int tid = threadIdx.x;
    const int n0 = blockIdx.x * 64;

    // ---- stage weights (coalesced uint4 copies, no converts) + node tile ----
    #pragma unroll
    for (int i = 0; i < 4; i++) {
        int u4 = i * 128 + tid;        // 512 uint4 over 64x64 halves
        int n = u4 >> 3;
        int c = (u4 & 7) * 8;
        *(uint4*)(sW1t + n * WS + c) = ((const uint4*)w1t)[u4];
        *(uint4*)(sW2t + n * WS + c) = ((const uint4*)w2t)[u4];
        uint4 v = make_uint4(0, 0, 0, 0);
        if (n0 + n < NN)
            v = *(const uint4*)(g_aggh + (size_t)(n0 + n) * DD + c);
        *(uint4*)(sT + n * WS + c) = v;
    }
    __syncthreads();

    const int w = tid >> 5;
    const int lane = tid & 31;
    const int g = lane >> 2;
    const int tg = lane & 3;
    const int row0 = w * 16 + g;
    const int row1 = row0 + 8;

    uint32_t a1f[4][4];
    #pragma unroll
    for (int kt = 0; kt < 4; kt++) {
        int k0 = kt * 16 + tg * 2;
        a1f[kt][0] = *(const uint32_t*)(sT + row0 * WS + k0);
        a1f[kt][1] = *(const uint32_t*)(sT + row1 * WS + k0);
        a1f[kt][2] = *(const uint32_t*)(sT + row0 * WS + k0 + 8);
        a1f[kt][3] = *(const uint32_t*)(sT + row1 * WS + k0 + 8);
    }

    float acc[8][4];

    // ---- GEMM1: h = T @ W1 + b1 ----
    #pragma unroll
    for (int nt = 0; nt < 8; nt++) {
        int col = nt * 8 + tg * 2;
        float2 bb = *(const float2*)(b1 + col);
        acc[nt][0] = bb.x; acc[nt][1] = bb.y;
        acc[nt][2] = bb.x; acc[nt][3] = bb.y;
        int cw = (nt * 8 + g) * WS;
        #pragma unroll
        for (int kt = 0; kt < 4; kt++) {
            int k0 = kt * 16 + tg * 2;
            uint32_t b0 = *(const uint32_t*)(sW1t + cw + k0);
            uint32_t b1r = *(const uint32_t*)(sW1t + cw + k0 + 8);
            hmma(acc[nt], a1f[kt], b0, b1r);
        }
    }

    // ---- tanh + repack C1 -> A2 fragments (pure registers) ----
    uint32_t a2f[4][4];
    #pragma unroll
    for (int kt = 0; kt < 4; kt++) {
        int e = 2 * kt;
        a2f[kt][0] = pack_h2(fast_tanh(acc[e][0]),     fast_tanh(acc[e][1]));
        a2f[kt][1] = pack_h2(fast_tanh(acc[e][2]),     fast_tanh(acc[e][3]));
        a2f[kt][2] = pack_h2(fast_tanh(acc[e + 1][0]), fast_tanh(acc[e + 1][1]));
        a2f[kt][3] = pack_h2(fast_tanh(acc[e + 1][2]), fast_tanh(acc[e + 1][3]));
    }

    // ---- GEMM2: y = H @ W2 + b2 ----
    #pragma unroll
    for (int nt = 0; nt < 8; nt++) {
        int col = nt * 8 + tg * 2;
        float2 bb = *(const float2*)(b2 + col);
        acc[nt][0] = bb.x; acc[nt][1] = bb.y;
        acc[nt][2] = bb.x; acc[nt][3] = bb.y;
        int cw = (nt * 8 + g) * WS;
        #pragma unroll
        for (int kt = 0; kt < 4; kt++) {
            int k0 = kt * 16 + tg * 2;
            uint32_t b0 = *(const uint32_t*)(sW2t + cw + k0);
            uint32_t b1r = *(const uint32_t*)(sW2t + cw + k0 + 8);
            hmma(acc[nt], a2f[kt], b0, b1r);
        }
    }

    // ---- store ----
    int gr0 = n0 + row0;
    int gr1 = n0 + row1;
    #pragma unroll
    for (int nt = 0; nt < 8; nt++) {
        int col = nt * 8 + tg * 2;
        if (out_half) {
            if (gr0 < NN)
                *(uint32_t*)(g_y0h + (size_t)gr0 * DD + col) =
                    pack_h2(acc[nt][0], acc[nt][1]);
            if (gr1 < NN)
                *(uint32_t*)(g_y0h + (size_t)gr1 * DD + col) =
                    pack_h2(acc[nt][2], acc[nt][3]);
        } else {
            if (gr0 < NN)
                *(float2*)(out + (size_t)gr0 * DD + col) =
                    make_float2(acc[nt][0], acc[nt][1]);
            if (gr1 < NN)
                *(float2*)(out + (size_t)gr1 * DD + col) =
                    make_float2(acc[nt][2], acc[nt][3]);
        }
    }
}

// ---------------------------------------------------------------------------
// launch — 7 kernels
// ---------------------------------------------------------------------------
extern "C" void kernel_launch(void* const* d_in, const int* in_sizes, int n_in,
                              void* d_out, int out_size) {
    const float* x    = (const float*)d_in[0];
    const int*   src  = (const int*)d_in[1];
    const int*   dst  = (const int*)d_in[2];
    const float* w1_0 = (const float*)d_in[3];
    const float* b1_0 = (const float*)d_in[4];
    const float* w2_0 = (const float*)d_in[5];
    const float* b2_0 = (const float*)d_in[6];
    const float* w1_1 = (const float*)d_in[7];
    const float* b1_1 = (const float*)d_in[8];
    const float* w2_1 = (const float*)d_in[9];
    const float* b2_1 = (const float*)d_in[10];
    float* out = (float*)d_out;

    const int edgeb = (NE + 255) / 256;
    const int gathb = (NN * 8 + 255) / 256;
    const int mlpb  = (NN + 63) / 64;

    convhist_kernel<<<edgeb, 256>>>(x, dst, w1_0, w2_0, w1_1, w2_1);
    scan_kernel<<<NCHUNK, SCAN_T>>>();
    fill_kernel<<<edgeb, 256>>>(src, dst);

    gather_kernel<<<gathb, 256>>>(/*in_scratch=*/0);
    mlp_kernel<<<mlpb, 128>>>(b1_0, b2_0, out, /*layer=*/0, /*out_half=*/1);

    gather_kernel<<<gathb, 256>>>(/*in_scratch=*/1);
    mlp_kernel<<<mlpb, 128>>>(b1_1, b2_1, out, /*layer=*/1, /*out_half=*/0);
}

// round 15
// speedup vs baseline: 1.3352x; 1.0301x over previous
#include <cuda_runtime.h>
#include <cuda_fp16.h>
#include <stdint.h>

#define NN 50000
#define NE 800000
#define DD 64

#define SCAN_T 1024
#define NCHUNK ((NN + SCAN_T - 1) / SCAN_T)   // 49

// scratch (no allocations allowed). Zero-initialized at module load.
// INVARIANT: g_cnt == 0 at entry of every kernel_launch call.
__device__ __half g_aggh[NN * DD];   // h_in = x + sum(neighbors), fp16
__device__ __half g_xh[NN * DD];     // fp16 copy of x
__device__ __half g_y0h[NN * DD];    // fp16 layer-0 output
__device__ __half g_wt[2][2][64 * 64]; // [layer][w1|w2] transposed fp16: [n][k]
__device__ int    g_cnt[NN];
__device__ int    g_rowptr[NN + 1];
__device__ int    g_col[NE];
__device__ int    g_pos[NE];

// ---------------------------------------------------------------------------
// fused conv (x -> fp16) + weight conversion (fp32 -> fp16 transposed)
// + degree histogram (records per-edge slot)
// ---------------------------------------------------------------------------
__global__ void __launch_bounds__(256)
convhist_kernel(const float* __restrict__ x, const int* __restrict__ dst,
                const float* __restrict__ w1_0, const float* __restrict__ w2_0,
                const float* __restrict__ w1_1, const float* __restrict__ w2_1) {
    int i = blockIdx.x * blockDim.x + threadIdx.x;
    if (i < NN * DD / 8) {
        float4 a = ((const float4*)x)[2 * i];
        float4 b = ((const float4*)x)[2 * i + 1];
        __half2 h[4];
        h[0] = __floats2half2_rn(a.x, a.y);
        h[1] = __floats2half2_rn(a.z, a.w);
        h[2] = __floats2half2_rn(b.x, b.y);
        h[3] = __floats2half2_rn(b.z, b.w);
        ((uint4*)g_xh)[i] = *(uint4*)h;
    }
    if (i < 4096) {
        int k = i >> 6, n = i & 63;        // w[i] = W[k][n]
        int to = n * 64 + k;               // transposed [n][k]
        g_wt[0][0][to] = __float2half(w1_0[i]);
        g_wt[0][1][to] = __float2half(w2_0[i]);
        g_wt[1][0][to] = __float2half(w1_1[i]);
        g_wt[1][1][to] = __float2half(w2_1[i]);
    }
    if (i < NE) {
        g_pos[i] = atomicAdd(&g_cnt[dst[i]], 1);
    }
}

// ---------------------------------------------------------------------------
// single-pass scan (block b redundantly reduces chunks [0,b) for its base)
// ---------------------------------------------------------------------------
__global__ void __launch_bounds__(SCAN_T)
scan_kernel() {
    __shared__ int s[SCAN_T];
    __shared__ int s_base;
    int b = blockIdx.x;
    int t = threadIdx.x;

    int pre = 0;
    for (int i = t; i < b * SCAN_T; i += SCAN_T) pre += g_cnt[i];
    s[t] = pre;
    __syncthreads();
    #pragma unroll
    for (int off = SCAN_T / 2; off > 0; off >>= 1) {
        if (t < off) s[t] += s[t + off];
        __syncthreads();
    }
    if (t == 0) s_base = s[0];
    __syncthreads();
    int base = s_base;
    __syncthreads();

    int i = b * SCAN_T + t;
    int v = (i < NN) ? g_cnt[i] : 0;
    s[t] = v;
    __syncthreads();
    #pragma unroll
    for (int off = 1; off < SCAN_T; off <<= 1) {
        int add = (t >= off) ? s[t - off] : 0;
        __syncthreads();
        s[t] += add;
        __syncthreads();
    }
    if (i < NN) g_rowptr[i + 1] = base + s[t];
    if (i == 0) g_rowptr[0] = 0;
}

// atomic-free fill; pos==0 edge resets g_cnt[d] for the next call
__global__ void fill_kernel(const int* __restrict__ src,
                            const int* __restrict__ dst) {
    int e = blockIdx.x * blockDim.x + threadIdx.x;
    if (e < NE) {
        int d = dst[e];
        int p = g_pos[e];
        g_col[g_rowptr[d] + p] = src[e];
        if (p == 0) g_cnt[d] = 0;
    }
}

// ---------------------------------------------------------------------------
// fp16 gather, 8-wide MLP: g_aggh[n] = X[n] + sum X[j]
// 8 lanes per node, each lane owns 8 halfs (16B). 8 independent LDG.128 in
// flight per thread before any consumption (fights long_scoreboard).
// ---------------------------------------------------------------------------
__device__ __forceinline__ void acc_add(float* a, uint4 v) {
    const __half2* h = (const __half2*)&v;
    #pragma unroll
    for (int i = 0; i < 4; i++) {
        float2 f = __half22float2(h[i]);
        a[2 * i]     += f.x;
        a[2 * i + 1] += f.y;
    }
}

__global__ void __launch_bounds__(256)
gather_kernel(int in_scratch) {
    const __half* __restrict__ base = in_scratch ? g_y0h : g_xh;
    int t = blockIdx.x * blockDim.x + threadIdx.x;
    int node = t >> 3;
    if (node >= NN) return;
    int colh = (t & 7) << 3;

    float acc[8] = {0.f};
    acc_add(acc, *(const uint4*)(base + (size_t)node * DD + colh));

    int p   = g_rowptr[node];
    int end = g_rowptr[node + 1];

    // 8-wide: issue all 8 loads, then consume
    for (; p + 7 < end; p += 8) {
        uint4 v[8];
        #pragma unroll
        for (int q = 0; q < 8; q++) {
            int j = g_col[p + q];
            v[q] = *(const uint4*)(base + (size_t)j * DD + colh);
        }
        #pragma unroll
        for (int q = 0; q < 8; q++) acc_add(acc, v[q]);
    }
    // 4-wide tail
    for (; p + 3 < end; p += 4) {
        uint4 v[4];
        #pragma unroll
        for (int q = 0; q < 4; q++) {
            int j = g_col[p + q];
            v[q] = *(const uint4*)(base + (size_t)j * DD + colh);
        }
        #pragma unroll
        for (int q = 0; q < 4; q++) acc_add(acc, v[q]);
    }
    for (; p < end; p++) {
        uint4 a = *(const uint4*)(base + (size_t)g_col[p] * DD + colh);
        acc_add(acc, a);
    }

    __half2 h[4];
    h[0] = __floats2half2_rn(acc[0], acc[1]);
    h[1] = __floats2half2_rn(acc[2], acc[3]);
    h[2] = __floats2half2_rn(acc[4], acc[5]);
    h[3] = __floats2half2_rn(acc[6], acc[7]);
    *(uint4*)(g_aggh + (size_t)node * DD + colh) = *(uint4*)h;
}

// ---------------------------------------------------------------------------
// HMMA MLP: out = tanh(T @ W1 + b1) @ W2 + b2, fp16 tensor cores, f32 acc.
// Weights pre-converted/transposed in gmem -> staging is pure uint4 copies.
// GEMM1 C-fragments ARE GEMM2 A-fragments -> tanh+repack in registers.
// ---------------------------------------------------------------------------
__device__ __forceinline__ float fast_tanh(float x) {
    float y;
    asm("tanh.approx.f32 %0, %1;" : "=f"(y) : "f"(x));
    return y;
}

__device__ __forceinline__ void hmma(float* c, const uint32_t* a,
                                     uint32_t b0, uint32_t b1) {
    asm volatile(
        "mma.sync.aligned.m16n8k16.row.col.f32.f16.f16.f32 "
        "{%0,%1,%2,%3},{%4,%5,%6,%7},{%8,%9},{%0,%1,%2,%3};"
        : "+f"(c[0]), "+f"(c[1]), "+f"(c[2]), "+f"(c[3])
        : "r"(a[0]), "r"(a[1]), "r"(a[2]), "r"(a[3]), "r"(b0), "r"(b1));
}

__device__ __forceinline__ uint32_t pack_h2(float lo, float hi) {
    __half2 h = __floats2half2_rn(lo, hi);
    return *(uint32_t*)&h;
}

#define WS 72   // padded half-stride (144B rows; conflict-free frag loads)

__global__ void __launch_bounds__(128)
mlp_kernel(const float* __restrict__ b1, const float* __restrict__ b2,
           float* __restrict__ out, int layer, int out_half) {
    __shared__ __half sW1t[64 * WS];   // sW1t[n][k] = W1[k][n]
    __shared__ __half sW2t[64 * WS];
    __shared__ __half sT[64 * WS];     // node tile, row-major fp16

    const __half* __restrict__ w1t = g_wt[layer][0];
    const __half* __restrict__ w2t = g_wt[layer][1];

    const int tid = threadIdx.x;
    const int n0 = blockIdx.x * 64;

    // ---- stage weights (coalesced uint4 copies, no converts) + node tile ----
    #pragma unroll
    for (int i = 0; i < 4; i++) {
        int u4 = i * 128 + tid;        // 512 uint4 over 64x64 halves
        int n = u4 >> 3;
        int c = (u4 & 7) * 8;
        *(uint4*)(sW1t + n * WS + c) = ((const uint4*)w1t)[u4];
        *(uint4*)(sW2t + n * WS + c) = ((const uint4*)w2t)[u4];
        uint4 v = make_uint4(0, 0, 0, 0);
        if (n0 + n < NN)
            v = *(const uint4*)(g_aggh + (size_t)(n0 + n) * DD + c);
        *(uint4*)(sT + n * WS + c) = v;
    }
    __syncthreads();

    const int w = tid >> 5;
    const int lane = tid & 31;
    const int g = lane >> 2;
    const int tg = lane & 3;
    const int row0 = w * 16 + g;
    const int row1 = row0 + 8;

    uint32_t a1f[4][4];
    #pragma unroll
    for (int kt = 0; kt < 4; kt++) {
        int k0 = kt * 16 + tg * 2;
        a1f[kt][0] = *(const uint32_t*)(sT + row0 * WS + k0);
        a1f[kt][1] = *(const uint32_t*)(sT + row1 * WS + k0);
        a1f[kt][2] = *(const uint32_t*)(sT + row0 * WS + k0 + 8);
        a1f[kt][3] = *(const uint32_t*)(sT + row1 * WS + k0 + 8);
    }

    float acc[8][4];

    // ---- GEMM1: h = T @ W1 + b1 ----
    #pragma unroll
    for (int nt = 0; nt < 8; nt++) {
        int col = nt * 8 + tg * 2;
        float2 bb = *(const float2*)(b1 + col);
        acc[nt][0] = bb.x; acc[nt][1] = bb.y;
        acc[nt][2] = bb.x; acc[nt][3] = bb.y;
        int cw = (nt * 8 + g) * WS;
        #pragma unroll
        for (int kt = 0; kt < 4; kt++) {
            int k0 = kt * 16 + tg * 2;
            uint32_t b0 = *(const uint32_t*)(sW1t + cw + k0);
            uint32_t b1r = *(const uint32_t*)(sW1t + cw + k0 + 8);
            hmma(acc[nt], a1f[kt], b0, b1r);
        }
    }

    // ---- tanh + repack C1 -> A2 fragments (pure registers) ----
    uint32_t a2f[4][4];
    #pragma unroll
    for (int kt = 0; kt < 4; kt++) {
        int e = 2 * kt;
        a2f[kt][0] = pack_h2(fast_tanh(acc[e][0]),     fast_tanh(acc[e][1]));
        a2f[kt][1] = pack_h2(fast_tanh(acc[e][2]),     fast_tanh(acc[e][3]));
        a2f[kt][2] = pack_h2(fast_tanh(acc[e + 1][0]), fast_tanh(acc[e + 1][1]));
        a2f[kt][3] = pack_h2(fast_tanh(acc[e + 1][2]), fast_tanh(acc[e + 1][3]));
    }

    // ---- GEMM2: y = H @ W2 + b2 ----
    #pragma unroll
    for (int nt = 0; nt < 8; nt++) {
        int col = nt * 8 + tg * 2;
        float2 bb = *(const float2*)(b2 + col);
        acc[nt][0] = bb.x; acc[nt][1] = bb.y;
        acc[nt][2] = bb.x; acc[nt][3] = bb.y;
        int cw = (nt * 8 + g) * WS;
        #pragma unroll
        for (int kt = 0; kt < 4; kt++) {
            int k0 = kt * 16 + tg * 2;
            uint32_t b0 = *(const uint32_t*)(sW2t + cw + k0);
            uint32_t b1r = *(const uint32_t*)(sW2t + cw + k0 + 8);
            hmma(acc[nt], a2f[kt], b0, b1r);
        }
    }

    // ---- store ----
    int gr0 = n0 + row0;
    int gr1 = n0 + row1;
    #pragma unroll
    for (int nt = 0; nt < 8; nt++) {
        int col = nt * 8 + tg * 2;
        if (out_half) {
            if (gr0 < NN)
                *(uint32_t*)(g_y0h + (size_t)gr0 * DD + col) =
                    pack_h2(acc[nt][0], acc[nt][1]);
            if (gr1 < NN)
                *(uint32_t*)(g_y0h + (size_t)gr1 * DD + col) =
                    pack_h2(acc[nt][2], acc[nt][3]);
        } else {
            if (gr0 < NN)
                *(float2*)(out + (size_t)gr0 * DD + col) =
                    make_float2(acc[nt][0], acc[nt][1]);
            if (gr1 < NN)
                *(float2*)(out + (size_t)gr1 * DD + col) =
                    make_float2(acc[nt][2], acc[nt][3]);
        }
    }
}

// ---------------------------------------------------------------------------
// launch — 7 kernels
// ---------------------------------------------------------------------------
extern "C" void kernel_launch(void* const* d_in, const int* in_sizes, int n_in,
                              void* d_out, int out_size) {
    const float* x    = (const float*)d_in[0];
    const int*   src  = (const int*)d_in[1];
    const int*   dst  = (const int*)d_in[2];
    const float* w1_0 = (const float*)d_in[3];
    const float* b1_0 = (const float*)d_in[4];
    const float* w2_0 = (const float*)d_in[5];
    const float* b2_0 = (const float*)d_in[6];
    const float* w1_1 = (const float*)d_in[7];
    const float* b1_1 = (const float*)d_in[8];
    const float* w2_1 = (const float*)d_in[9];
    const float* b2_1 = (const float*)d_in[10];
    float* out = (float*)d_out;

    const int edgeb = (NE + 255) / 256;
    const int gathb = (NN * 8 + 255) / 256;
    const int mlpb  = (NN + 63) / 64;

    convhist_kernel<<<edgeb, 256>>>(x, dst, w1_0, w2_0, w1_1, w2_1);
    scan_kernel<<<NCHUNK, SCAN_T>>>();
    fill_kernel<<<edgeb, 256>>>(src, dst);

    gather_kernel<<<gathb, 256>>>(/*in_scratch=*/0);
    mlp_kernel<<<mlpb, 128>>>(b1_0, b2_0, out, /*layer=*/0, /*out_half=*/1);

    gather_kernel<<<gathb, 256>>>(/*in_scratch=*/1);
    mlp_kernel<<<mlpb, 128>>>(b1_1, b2_1, out, /*layer=*/1, /*out_half=*/0);
}

// round 16
// speedup vs baseline: 1.5106x; 1.1314x over previous
#include <cuda_runtime.h>
#include <cuda_fp16.h>
#include <stdint.h>

#define NN 50000
#define NE 800000
#define DD 64
#define CAP 48
#define OVF 65536

// scratch (no allocations allowed). Zero-initialized at module load.
// INVARIANT: g_cnt == 0 and g_ovfcnt == 0 at entry of every kernel_launch
// call (layer-1 mlp_kernel resets them).
__device__ __half g_aggh[NN * DD];   // h_in = x + sum(neighbors), fp16
__device__ __half g_xh[NN * DD];     // fp16 copy of x
__device__ __half g_y0h[NN * DD];    // fp16 layer-0 output
__device__ __half g_wt[2][2][64 * 64]; // [layer][w1|w2] transposed fp16: [n][k]
__device__ int    g_cnt[NN];
__device__ int    g_bucket[NN][CAP]; // 9.6 MB in-neighbor buckets
__device__ int2   g_ovf[OVF];        // (dst, src) overflow edges
__device__ int    g_ovfcnt;

// ---------------------------------------------------------------------------
// fused conv (x -> fp16) + weight conversion + bucket fill (replaces CSR)
// ---------------------------------------------------------------------------
__global__ void __launch_bounds__(256)
convhist_kernel(const float* __restrict__ x,
                const int* __restrict__ src, const int* __restrict__ dst,
                const float* __restrict__ w1_0, const float* __restrict__ w2_0,
                const float* __restrict__ w1_1, const float* __restrict__ w2_1) {
    int i = blockIdx.x * blockDim.x + threadIdx.x;
    if (i < NN * DD / 8) {
        float4 a = ((const float4*)x)[2 * i];
        float4 b = ((const float4*)x)[2 * i + 1];
        __half2 h[4];
        h[0] = __floats2half2_rn(a.x, a.y);
        h[1] = __floats2half2_rn(a.z, a.w);
        h[2] = __floats2half2_rn(b.x, b.y);
        h[3] = __floats2half2_rn(b.z, b.w);
        ((uint4*)g_xh)[i] = *(uint4*)h;
    }
    if (i < 4096) {
        int k = i >> 6, n = i & 63;        // w[i] = W[k][n]
        int to = n * 64 + k;               // transposed [n][k]
        g_wt[0][0][to] = __float2half(w1_0[i]);
        g_wt[0][1][to] = __float2half(w2_0[i]);
        g_wt[1][0][to] = __float2half(w1_1[i]);
        g_wt[1][1][to] = __float2half(w2_1[i]);
    }
    if (i < NE) {
        int d = dst[i];
        int s = src[i];
        int p = atomicAdd(&g_cnt[d], 1);
        if (p < CAP) {
            g_bucket[d][p] = s;
        } else {
            int o = atomicAdd(&g_ovfcnt, 1);
            if (o < OVF) g_ovf[o] = make_int2(d, s);
        }
    }
}

// ---------------------------------------------------------------------------
// fp16 gather from buckets: g_aggh[n] = X[n] + sum X[j]
// 8 lanes per node, 16B per lane; 8 independent row loads in flight;
// int4 index loads (bucket rows are 16B-aligned: CAP=48).
// ---------------------------------------------------------------------------
__device__ __forceinline__ void acc_add(float* a, uint4 v) {
    const __half2* h = (const __half2*)&v;
    #pragma unroll
    for (int i = 0; i < 4; i++) {
        float2 f = __half22float2(h[i]);
        a[2 * i]     += f.x;
        a[2 * i + 1] += f.y;
    }
}

__global__ void __launch_bounds__(256)
gather_kernel(int in_scratch) {
    const __half* __restrict__ base = in_scratch ? g_y0h : g_xh;
    int t = blockIdx.x * blockDim.x + threadIdx.x;
    int node = t >> 3;
    if (node >= NN) return;
    int colh = (t & 7) << 3;

    float acc[8] = {0.f};
    acc_add(acc, *(const uint4*)(base + (size_t)node * DD + colh));

    int deg = g_cnt[node];
    int m = deg < CAP ? deg : CAP;
    const int* brow = g_bucket[node];

    int p = 0;
    for (; p + 7 < m; p += 8) {
        int4 i0 = *(const int4*)(brow + p);
        int4 i1 = *(const int4*)(brow + p + 4);
        uint4 v[8];
        v[0] = *(const uint4*)(base + (size_t)i0.x * DD + colh);
        v[1] = *(const uint4*)(base + (size_t)i0.y * DD + colh);
        v[2] = *(const uint4*)(base + (size_t)i0.z * DD + colh);
        v[3] = *(const uint4*)(base + (size_t)i0.w * DD + colh);
        v[4] = *(const uint4*)(base + (size_t)i1.x * DD + colh);
        v[5] = *(const uint4*)(base + (size_t)i1.y * DD + colh);
        v[6] = *(const uint4*)(base + (size_t)i1.z * DD + colh);
        v[7] = *(const uint4*)(base + (size_t)i1.w * DD + colh);
        #pragma unroll
        for (int q = 0; q < 8; q++) acc_add(acc, v[q]);
    }
    for (; p + 3 < m; p += 4) {
        int4 i0 = *(const int4*)(brow + p);
        uint4 v[4];
        v[0] = *(const uint4*)(base + (size_t)i0.x * DD + colh);
        v[1] = *(const uint4*)(base + (size_t)i0.y * DD + colh);
        v[2] = *(const uint4*)(base + (size_t)i0.z * DD + colh);
        v[3] = *(const uint4*)(base + (size_t)i0.w * DD + colh);
        #pragma unroll
        for (int q = 0; q < 4; q++) acc_add(acc, v[q]);
    }
    for (; p < m; p++) {
        uint4 v = *(const uint4*)(base + (size_t)brow[p] * DD + colh);
        acc_add(acc, v);
    }

    if (deg > CAP) {   // practically never taken; correctness fallback
        int oc = g_ovfcnt;
        if (oc > OVF) oc = OVF;
        for (int o = 0; o < oc; o++) {
            int2 e = g_ovf[o];
            if (e.x == node) {
                uint4 v = *(const uint4*)(base + (size_t)e.y * DD + colh);
                acc_add(acc, v);
            }
        }
    }

    __half2 h[4];
    h[0] = __floats2half2_rn(acc[0], acc[1]);
    h[1] = __floats2half2_rn(acc[2], acc[3]);
    h[2] = __floats2half2_rn(acc[4], acc[5]);
    h[3] = __floats2half2_rn(acc[6], acc[7]);
    *(uint4*)(g_aggh + (size_t)node * DD + colh) = *(uint4*)h;
}

// ---------------------------------------------------------------------------
// HMMA MLP: out = tanh(T @ W1 + b1) @ W2 + b2, fp16 tensor cores, f32 acc.
// Layer 1 additionally resets g_cnt / g_ovfcnt for the next call.
// ---------------------------------------------------------------------------
__device__ __forceinline__ float fast_tanh(float x) {
    float y;
    asm("tanh.approx.f32 %0, %1;" : "=f"(y) : "f"(x));
    return y;
}

__device__ __forceinline__ void hmma(float* c, const uint32_t* a,
                                     uint32_t b0, uint32_t b1) {
    asm volatile(
        "mma.sync.aligned.m16n8k16.row.col.f32.f16.f16.f32 "
        "{%0,%1,%2,%3},{%4,%5,%6,%7},{%8,%9},{%0,%1,%2,%3};"
        : "+f"(c[0]), "+f"(c[1]), "+f"(c[2]), "+f"(c[3])
        : "r"(a[0]), "r"(a[1]), "r"(a[2]), "r"(a[3]), "r"(b0), "r"(b1));
}

__device__ __forceinline__ uint32_t pack_h2(float lo, float hi) {
    __half2 h = __floats2half2_rn(lo, hi);
    return *(uint32_t*)&h;
}

#define WS 72   // padded half-stride (144B rows; conflict-free frag loads)

__global__ void __launch_bounds__(128)
mlp_kernel(const float* __restrict__ b1, const float* __restrict__ b2,
           float* __restrict__ out, int layer, int out_half) {
    __shared__ __half sW1t[64 * WS];   // sW1t[n][k] = W1[k][n]
    __shared__ __half sW2t[64 * WS];
    __shared__ __half sT[64 * WS];     // node tile, row-major fp16

    const __half* __restrict__ w1t = g_wt[layer][0];
    const __half* __restrict__ w2t = g_wt[layer][1];

    const int tid = threadIdx.x;
    const int n0 = blockIdx.x * 64;

    // ---- counter reset for next call (layer 1 only; after last gather) ----
    if (layer == 1) {
        if (tid < 64 && n0 + tid < NN) g_cnt[n0 + tid] = 0;
        if (tid == 64 && blockIdx.x == 0) g_ovfcnt = 0;
    }

    // ---- stage weights (coalesced uint4 copies) + node tile ----
    #pragma unroll
    for (int i = 0; i < 4; i++) {
        int u4 = i * 128 + tid;        // 512 uint4 over 64x64 halves
        int n = u4 >> 3;
        int c = (u4 & 7) * 8;
        *(uint4*)(sW1t + n * WS + c) = ((const uint4*)w1t)[u4];
        *(uint4*)(sW2t + n * WS + c) = ((const uint4*)w2t)[u4];
        uint4 v = make_uint4(0, 0, 0, 0);
        if (n0 + n < NN)
            v = *(const uint4*)(g_aggh + (size_t)(n0 + n) * DD + c);
        *(uint4*)(sT + n * WS + c) = v;
    }
    __syncthreads();

    const int w = tid >> 5;
    const int lane = tid & 31;
    const int g = lane >> 2;
    const int tg = lane & 3;
    const int row0 = w * 16 + g;
    const int row1 = row0 + 8;

    uint32_t a1f[4][4];
    #pragma unroll
    for (int kt = 0; kt < 4; kt++) {
        int k0 = kt * 16 + tg * 2;
        a1f[kt][0] = *(const uint32_t*)(sT + row0 * WS + k0);
        a1f[kt][1] = *(const uint32_t*)(sT + row1 * WS + k0);
        a1f[kt][2] = *(const uint32_t*)(sT + row0 * WS + k0 + 8);
        a1f[kt][3] = *(const uint32_t*)(sT + row1 * WS + k0 + 8);
    }

    float acc[8][4];

    // ---- GEMM1: h = T @ W1 + b1 ----
    #pragma unroll
    for (int nt = 0; nt < 8; nt++) {
        int col = nt * 8 + tg * 2;
        float2 bb = *(const float2*)(b1 + col);
        acc[nt][0] = bb.x; acc[nt][1] = bb.y;
        acc[nt][2] = bb.x; acc[nt][3] = bb.y;
        int cw = (nt * 8 + g) * WS;
        #pragma unroll
        for (int kt = 0; kt < 4; kt++) {
            int k0 = kt * 16 + tg * 2;
            uint32_t b0 = *(const uint32_t*)(sW1t + cw + k0);
            uint32_t b1r = *(const uint32_t*)(sW1t + cw + k0 + 8);
            hmma(acc[nt], a1f[kt], b0, b1r);
        }
    }

    // ---- tanh + repack C1 -> A2 fragments (pure registers) ----
    uint32_t a2f[4][4];
    #pragma unroll
    for (int kt = 0; kt < 4; kt++) {
        int e = 2 * kt;
        a2f[kt][0] = pack_h2(fast_tanh(acc[e][0]),     fast_tanh(acc[e][1]));
        a2f[kt][1] = pack_h2(fast_tanh(acc[e][2]),     fast_tanh(acc[e][3]));
        a2f[kt][2] = pack_h2(fast_tanh(acc[e + 1][0]), fast_tanh(acc[e + 1][1]));
        a2f[kt][3] = pack_h2(fast_tanh(acc[e + 1][2]), fast_tanh(acc[e + 1][3]));
    }

    // ---- GEMM2: y = H @ W2 + b2 ----
    #pragma unroll
    for (int nt = 0; nt < 8; nt++) {
        int col = nt * 8 + tg * 2;
        float2 bb = *(const float2*)(b2 + col);
        acc[nt][0] = bb.x; acc[nt][1] = bb.y;
        acc[nt][2] = bb.x; acc[nt][3] = bb.y;
        int cw = (nt * 8 + g) * WS;
        #pragma unroll
        for (int kt = 0; kt < 4; kt++) {
            int k0 = kt * 16 + tg * 2;
            uint32_t b0 = *(const uint32_t*)(sW2t + cw + k0);
            uint32_t b1r = *(const uint32_t*)(sW2t + cw + k0 + 8);
            hmma(acc[nt], a2f[kt], b0, b1r);
        }
    }

    // ---- store ----
    int gr0 = n0 + row0;
    int gr1 = n0 + row1;
    #pragma unroll
    for (int nt = 0; nt < 8; nt++) {
        int col = nt * 8 + tg * 2;
        if (out_half) {
            if (gr0 < NN)
                *(uint32_t*)(g_y0h + (size_t)gr0 * DD + col) =
                    pack_h2(acc[nt][0], acc[nt][1]);
            if (gr1 < NN)
                *(uint32_t*)(g_y0h + (size_t)gr1 * DD + col) =
                    pack_h2(acc[nt][2], acc[nt][3]);
        } else {
            if (gr0 < NN)
                *(float2*)(out + (size_t)gr0 * DD + col) =
                    make_float2(acc[nt][0], acc[nt][1]);
            if (gr1 < NN)
                *(float2*)(out + (size_t)gr1 * DD + col) =
                    make_float2(acc[nt][2], acc[nt][3]);
        }
    }
}

// ---------------------------------------------------------------------------
// launch — 5 kernels
// ---------------------------------------------------------------------------
extern "C" void kernel_launch(void* const* d_in, const int* in_sizes, int n_in,
                              void* d_out, int out_size) {
    const float* x    = (const float*)d_in[0];
    const int*   src  = (const int*)d_in[1];
    const int*   dst  = (const int*)d_in[2];
    const float* w1_0 = (const float*)d_in[3];
    const float* b1_0 = (const float*)d_in[4];
    const float* w2_0 = (const float*)d_in[5];
    const float* b2_0 = (const float*)d_in[6];
    const float* w1_1 = (const float*)d_in[7];
    const float* b1_1 = (const float*)d_in[8];
    const float* w2_1 = (const float*)d_in[9];
    const float* b2_1 = (const float*)d_in[10];
    float* out = (float*)d_out;

    const int edgeb = (NE + 255) / 256;
    const int gathb = (NN * 8 + 255) / 256;
    const int mlpb  = (NN + 63) / 64;

    convhist_kernel<<<edgeb, 256>>>(x, src, dst, w1_0, w2_0, w1_1, w2_1);

    gather_kernel<<<gathb, 256>>>(/*in_scratch=*/0);
    mlp_kernel<<<mlpb, 128>>>(b1_0, b2_0, out, /*layer=*/0, /*out_half=*/1);

    gather_kernel<<<gathb, 256>>>(/*in_scratch=*/1);
    mlp_kernel<<<mlpb, 128>>>(b1_1, b2_1, out, /*layer=*/1, /*out_half=*/0);
}

// round 17
// speedup vs baseline: 1.5122x; 1.0011x over previous
#include <cuda_runtime.h>
#include <cuda_fp16.h>
#include <stdint.h>

#define NN 50000
#define NE 800000
#define DD 64
#define CAP 48
#define OVF 65536

// scratch (no allocations allowed). Zero-initialized at module load.
// INVARIANT: g_cnt == 0 and g_ovfcnt == 0 at entry of every kernel_launch
// call (layer-1 mlp_kernel resets them).
__device__ __half g_aggh[NN * DD];   // h_in = x + sum(neighbors), fp16
__device__ __half g_xh[NN * DD];     // fp16 copy of x
__device__ __half g_y0h[NN * DD];    // fp16 layer-0 output
__device__ __half g_wt[2][2][64 * 64]; // [layer][w1|w2] transposed fp16: [n][k]
__device__ int    g_cnt[NN];
__device__ int    g_bucket[NN][CAP]; // 9.6 MB in-neighbor buckets
__device__ int2   g_ovf[OVF];        // (dst, src) overflow edges
__device__ int    g_ovfcnt;

// ---------------------------------------------------------------------------
// fused conv (x -> fp16) + weight conversion + bucket fill (replaces CSR)
// ---------------------------------------------------------------------------
__global__ void __launch_bounds__(256)
convhist_kernel(const float* __restrict__ x,
                const int* __restrict__ src, const int* __restrict__ dst,
                const float* __restrict__ w1_0, const float* __restrict__ w2_0,
                const float* __restrict__ w1_1, const float* __restrict__ w2_1) {
    int i = blockIdx.x * blockDim.x + threadIdx.x;
    if (i < NN * DD / 8) {
        float4 a = ((const float4*)x)[2 * i];
        float4 b = ((const float4*)x)[2 * i + 1];
        __half2 h[4];
        h[0] = __floats2half2_rn(a.x, a.y);
        h[1] = __floats2half2_rn(a.z, a.w);
        h[2] = __floats2half2_rn(b.x, b.y);
        h[3] = __floats2half2_rn(b.z, b.w);
        ((uint4*)g_xh)[i] = *(uint4*)h;
    }
    if (i < 4096) {
        int k = i >> 6, n = i & 63;        // w[i] = W[k][n]
        int to = n * 64 + k;               // transposed [n][k]
        g_wt[0][0][to] = __float2half(w1_0[i]);
        g_wt[0][1][to] = __float2half(w2_0[i]);
        g_wt[1][0][to] = __float2half(w1_1[i]);
        g_wt[1][1][to] = __float2half(w2_1[i]);
    }
    if (i < NE) {
        int d = dst[i];
        int s = src[i];
        int p = atomicAdd(&g_cnt[d], 1);
        if (p < CAP) {
            g_bucket[d][p] = s;
        } else {
            int o = atomicAdd(&g_ovfcnt, 1);
            if (o < OVF) g_ovf[o] = make_int2(d, s);
        }
    }
}

// ---------------------------------------------------------------------------
// fp16 gather from buckets, grid-stride (exactly one wave -> full-occupancy
// latency hiding, no low-occ tail): g_aggh[n] = X[n] + sum X[j]
// 8 lanes per node, 16B per lane; 8 independent row loads in flight.
// ---------------------------------------------------------------------------
#define GATH_BLOCKS 1184   // 148 SMs x 8 blocks of 256 = one full wave

__device__ __forceinline__ void acc_add(float* a, uint4 v) {
    const __half2* h = (const __half2*)&v;
    #pragma unroll
    for (int i = 0; i < 4; i++) {
        float2 f = __half22float2(h[i]);
        a[2 * i]     += f.x;
        a[2 * i + 1] += f.y;
    }
}

__global__ void __launch_bounds__(256)
gather_kernel(int in_scratch) {
    const __half* __restrict__ base = in_scratch ? g_y0h : g_xh;
    const int stride = GATH_BLOCKS * 256;

    for (int t = blockIdx.x * blockDim.x + threadIdx.x; t < NN * 8;
         t += stride) {
        int node = t >> 3;
        int colh = (t & 7) << 3;

        float acc[8] = {0.f};
        acc_add(acc, *(const uint4*)(base + (size_t)node * DD + colh));

        int deg = g_cnt[node];
        int m = deg < CAP ? deg : CAP;
        const int* brow = g_bucket[node];

        int p = 0;
        for (; p + 7 < m; p += 8) {
            int4 i0 = *(const int4*)(brow + p);
            int4 i1 = *(const int4*)(brow + p + 4);
            uint4 v[8];
            v[0] = *(const uint4*)(base + (size_t)i0.x * DD + colh);
            v[1] = *(const uint4*)(base + (size_t)i0.y * DD + colh);
            v[2] = *(const uint4*)(base + (size_t)i0.z * DD + colh);
            v[3] = *(const uint4*)(base + (size_t)i0.w * DD + colh);
            v[4] = *(const uint4*)(base + (size_t)i1.x * DD + colh);
            v[5] = *(const uint4*)(base + (size_t)i1.y * DD + colh);
            v[6] = *(const uint4*)(base + (size_t)i1.z * DD + colh);
            v[7] = *(const uint4*)(base + (size_t)i1.w * DD + colh);
            #pragma unroll
            for (int q = 0; q < 8; q++) acc_add(acc, v[q]);
        }
        for (; p + 3 < m; p += 4) {
            int4 i0 = *(const int4*)(brow + p);
            uint4 v[4];
            v[0] = *(const uint4*)(base + (size_t)i0.x * DD + colh);
            v[1] = *(const uint4*)(base + (size_t)i0.y * DD + colh);
            v[2] = *(const uint4*)(base + (size_t)i0.z * DD + colh);
            v[3] = *(const uint4*)(base + (size_t)i0.w * DD + colh);
            #pragma unroll
            for (int q = 0; q < 4; q++) acc_add(acc, v[q]);
        }
        for (; p < m; p++) {
            uint4 v = *(const uint4*)(base + (size_t)brow[p] * DD + colh);
            acc_add(acc, v);
        }

        if (deg > CAP) {   // practically never taken; correctness fallback
            int oc = g_ovfcnt;
            if (oc > OVF) oc = OVF;
            for (int o = 0; o < oc; o++) {
                int2 e = g_ovf[o];
                if (e.x == node) {
                    uint4 v = *(const uint4*)(base + (size_t)e.y * DD + colh);
                    acc_add(acc, v);
                }
            }
        }

        __half2 h[4];
        h[0] = __floats2half2_rn(acc[0], acc[1]);
        h[1] = __floats2half2_rn(acc[2], acc[3]);
        h[2] = __floats2half2_rn(acc[4], acc[5]);
        h[3] = __floats2half2_rn(acc[6], acc[7]);
        *(uint4*)(g_aggh + (size_t)node * DD + colh) = *(uint4*)h;
    }
}

// ---------------------------------------------------------------------------
// HMMA MLP: out = tanh(T @ W1 + b1) @ W2 + b2, fp16 tensor cores, f32 acc.
// Layer 1 additionally resets g_cnt / g_ovfcnt for the next call.
// ---------------------------------------------------------------------------
__device__ __forceinline__ float fast_tanh(float x) {
    float y;
    asm("tanh.approx.f32 %0, %1;" : "=f"(y) : "f"(x));
    return y;
}

__device__ __forceinline__ void hmma(float* c, const uint32_t* a,
                                     uint32_t b0, uint32_t b1) {
    asm volatile(
        "mma.sync.aligned.m16n8k16.row.col.f32.f16.f16.f32 "
        "{%0,%1,%2,%3},{%4,%5,%6,%7},{%8,%9},{%0,%1,%2,%3};"
        : "+f"(c[0]), "+f"(c[1]), "+f"(c[2]), "+f"(c[3])
        : "r"(a[0]), "r"(a[1]), "r"(a[2]), "r"(a[3]), "r"(b0), "r"(b1));
}

__device__ __forceinline__ uint32_t pack_h2(float lo, float hi) {
    __half2 h = __floats2half2_rn(lo, hi);
    return *(uint32_t*)&h;
}

#define WS 72   // padded half-stride (144B rows; conflict-free frag loads)

__global__ void __launch_bounds__(128)
mlp_kernel(const float* __restrict__ b1, const float* __restrict__ b2,
           float* __restrict__ out, int layer, int out_half) {
    __shared__ __half sW1t[64 * WS];   // sW1t[n][k] = W1[k][n]
    __shared__ __half sW2t[64 * WS];
    __shared__ __half sT[64 * WS];     // node tile, row-major fp16

    const __half* __restrict__ w1t = g_wt[layer][0];
    const __half* __restrict__ w2t = g_wt[layer][1];

    const int tid = threadIdx.x;
    const int n0 = blockIdx.x * 64;

    // ---- counter reset for next call (layer 1 only; after last gather) ----
    if (layer == 1) {
        if (tid < 64 && n0 + tid < NN) g_cnt[n0 + tid] = 0;
        if (tid == 64 && blockIdx.x == 0) g_ovfcnt = 0;
    }

    // ---- stage weights (coalesced uint4 copies) + node tile ----
    #pragma unroll
    for (int i = 0; i < 4; i++) {
        int u4 = i * 128 + tid;        // 512 uint4 over 64x64 halves
        int n = u4 >> 3;
        int c = (u4 & 7) * 8;
        *(uint4*)(sW1t + n * WS + c) = ((const uint4*)w1t)[u4];
        *(uint4*)(sW2t + n * WS + c) = ((const uint4*)w2t)[u4];
        uint4 v = make_uint4(0, 0, 0, 0);
        if (n0 + n < NN)
            v = *(const uint4*)(g_aggh + (size_t)(n0 + n) * DD + c);
        *(uint4*)(sT + n * WS + c) = v;
    }
    __syncthreads();

    const int w = tid >> 5;
    const int lane = tid & 31;
    const int g = lane >> 2;
    const int tg = lane & 3;
    const int row0 = w * 16 + g;
    const int row1 = row0 + 8;

    uint32_t a1f[4][4];
    #pragma unroll
    for (int kt = 0; kt < 4; kt++) {
        int k0 = kt * 16 + tg * 2;
        a1f[kt][0] = *(const uint32_t*)(sT + row0 * WS + k0);
        a1f[kt][1] = *(const uint32_t*)(sT + row1 * WS + k0);
        a1f[kt][2] = *(const uint32_t*)(sT + row0 * WS + k0 + 8);
        a1f[kt][3] = *(const uint32_t*)(sT + row1 * WS + k0 + 8);
    }

    float acc[8][4];

    // ---- GEMM1: h = T @ W1 + b1 ----
    #pragma unroll
    for (int nt = 0; nt < 8; nt++) {
        int col = nt * 8 + tg * 2;
        float2 bb = *(const float2*)(b1 + col);
        acc[nt][0] = bb.x; acc[nt][1] = bb.y;
        acc[nt][2] = bb.x; acc[nt][3] = bb.y;
        int cw = (nt * 8 + g) * WS;
        #pragma unroll
        for (int kt = 0; kt < 4; kt++) {
            int k0 = kt * 16 + tg * 2;
            uint32_t b0 = *(const uint32_t*)(sW1t + cw + k0);
            uint32_t b1r = *(const uint32_t*)(sW1t + cw + k0 + 8);
            hmma(acc[nt], a1f[kt], b0, b1r);
        }
    }

    // ---- tanh + repack C1 -> A2 fragments (pure registers) ----
    uint32_t a2f[4][4];
    #pragma unroll
    for (int kt = 0; kt < 4; kt++) {
        int e = 2 * kt;
        a2f[kt][0] = pack_h2(fast_tanh(acc[e][0]),     fast_tanh(acc[e][1]));
        a2f[kt][1] = pack_h2(fast_tanh(acc[e][2]),     fast_tanh(acc[e][3]));
        a2f[kt][2] = pack_h2(fast_tanh(acc[e + 1][0]), fast_tanh(acc[e + 1][1]));
        a2f[kt][3] = pack_h2(fast_tanh(acc[e + 1][2]), fast_tanh(acc[e + 1][3]));
    }

    // ---- GEMM2: y = H @ W2 + b2 ----
    #pragma unroll
    for (int nt = 0; nt < 8; nt++) {
        int col = nt * 8 + tg * 2;
        float2 bb = *(const float2*)(b2 + col);
        acc[nt][0] = bb.x; acc[nt][1] = bb.y;
        acc[nt][2] = bb.x; acc[nt][3] = bb.y;
        int cw = (nt * 8 + g) * WS;
        #pragma unroll
        for (int kt = 0; kt < 4; kt++) {
            int k0 = kt * 16 + tg * 2;
            uint32_t b0 = *(const uint32_t*)(sW2t + cw + k0);
            uint32_t b1r = *(const uint32_t*)(sW2t + cw + k0 + 8);
            hmma(acc[nt], a2f[kt], b0, b1r);
        }
    }

    // ---- store ----
    int gr0 = n0 + row0;
    int gr1 = n0 + row1;
    #pragma unroll
    for (int nt = 0; nt < 8; nt++) {
        int col = nt * 8 + tg * 2;
        if (out_half) {
            if (gr0 < NN)
                *(uint32_t*)(g_y0h + (size_t)gr0 * DD + col) =
                    pack_h2(acc[nt][0], acc[nt][1]);
            if (gr1 < NN)
                *(uint32_t*)(g_y0h + (size_t)gr1 * DD + col) =
                    pack_h2(acc[nt][2], acc[nt][3]);
        } else {
            if (gr0 < NN)
                *(float2*)(out + (size_t)gr0 * DD + col) =
                    make_float2(acc[nt][0], acc[nt][1]);
            if (gr1 < NN)
                *(float2*)(out + (size_t)gr1 * DD + col) =
                    make_float2(acc[nt][2], acc[nt][3]);
        }
    }
}

// ---------------------------------------------------------------------------
// launch — 5 kernels
// ---------------------------------------------------------------------------
extern "C" void kernel_launch(void* const* d_in, const int* in_sizes, int n_in,
                              void* d_out, int out_size) {
    const float* x    = (const float*)d_in[0];
    const int*   src  = (const int*)d_in[1];
    const int*   dst  = (const int*)d_in[2];
    const float* w1_0 = (const float*)d_in[3];
    const float* b1_0 = (const float*)d_in[4];
    const float* w2_0 = (const float*)d_in[5];
    const float* b2_0 = (const float*)d_in[6];
    const float* w1_1 = (const float*)d_in[7];
    const float* b1_1 = (const float*)d_in[8];
    const float* w2_1 = (const float*)d_in[9];
    const float* b2_1 = (const float*)d_in[10];
    float* out = (float*)d_out;

    const int edgeb = (NE + 255) / 256;
    const int mlpb  = (NN + 63) / 64;

    convhist_kernel<<<edgeb, 256>>>(x, src, dst, w1_0, w2_0, w1_1, w2_1);

    gather_kernel<<<GATH_BLOCKS, 256>>>(/*in_scratch=*/0);
    mlp_kernel<<<mlpb, 128>>>(b1_0, b2_0, out, /*layer=*/0, /*out_half=*/1);

    gather_kernel<<<GATH_BLOCKS, 256>>>(/*in_scratch=*/1);
    mlp_kernel<<<mlpb, 128>>>(b1_1, b2_1, out, /*layer=*/1, /*out_half=*/0);
}